// round 2
// baseline (speedup 1.0000x reference)
#include <cuda_runtime.h>
#include <math.h>

#define NQ  10
#define DIM 1024
#define NL  4
#define NT  512

__device__ __forceinline__ float2 cmul(float2 a, float2 b) {
    return make_float2(a.x * b.x - a.y * b.y, a.x * b.y + a.y * b.x);
}

__global__ __launch_bounds__(NT) void qsim_kernel(
    const float* __restrict__ inputs,   // [B, 10]
    const float* __restrict__ weights,  // [4, 10, 3]
    float* __restrict__ out)            // [B, 10]
{
    __shared__ float2 s[DIM];            // statevector, 8 KB
    __shared__ float2 U[NL][NQ][4];      // fused per-(layer,qubit) 2x2, 1.25 KB
    __shared__ float  zsum[NQ];

    const int b = blockIdx.x;
    const int t = threadIdx.x;

    // init |0...0>
    s[t]      = make_float2(0.f, 0.f);
    s[t + NT] = make_float2(0.f, 0.f);
    if (t == 0) s[0] = make_float2(1.f, 0.f);

    // ---- build all fused U[l][q] = RZ(w2) RY(w1) RX(w0) RY(x_q) up front ----
    if (t < NL * NQ) {
        const int l = t / NQ;
        const int q = t % NQ;
        float x = inputs[b * NQ + q];
        x = fminf(fmaxf(x, -3.14159265358979323846f), 3.14159265358979323846f);
        float sx, cx; sincosf(0.5f * x, &sx, &cx);
        const float* w = weights + (l * NQ + q) * 3;
        float sa, ca; sincosf(0.5f * w[0], &sa, &ca);
        float sb, cb; sincosf(0.5f * w[1], &sb, &cb);
        float sc, cc; sincosf(0.5f * w[2], &sc, &cc);
        // M1 = RX(a) * RY(x)
        float2 m00 = make_float2( ca * cx, -sa * sx);
        float2 m01 = make_float2(-ca * sx, -sa * cx);
        float2 m10 = make_float2( ca * sx, -sa * cx);
        float2 m11 = make_float2( ca * cx,  sa * sx);
        // M2 = RY(b) * M1   (real scalar rows)
        float2 n00 = make_float2(cb * m00.x - sb * m10.x, cb * m00.y - sb * m10.y);
        float2 n01 = make_float2(cb * m01.x - sb * m11.x, cb * m01.y - sb * m11.y);
        float2 n10 = make_float2(sb * m00.x + cb * m10.x, sb * m00.y + cb * m10.y);
        float2 n11 = make_float2(sb * m01.x + cb * m11.x, sb * m01.y + cb * m11.y);
        // M3 = RZ(c) * M2: row0 *= e^{-ic}, row1 *= e^{+ic}
        float2 e0 = make_float2(cc, -sc), e1 = make_float2(cc, sc);
        U[l][q][0] = cmul(e0, n00);
        U[l][q][1] = cmul(e0, n01);
        U[l][q][2] = cmul(e1, n10);
        U[l][q][3] = cmul(e1, n11);
    }
    __syncthreads();

    for (int l = 0; l < NL; ++l) {
        // ---- 10 fused single-qubit gate sweeps ----
        #pragma unroll
        for (int q = 0; q < NQ; ++q) {
            const int shift  = 9 - q;            // bit position of qubit q
            const int stride = 1 << shift;
            const int i0 = ((t >> shift) << (shift + 1)) | (t & (stride - 1));
            const int i1 = i0 + stride;
            const float2 a = s[i0];
            const float2 c = s[i1];
            const float2 u00 = U[l][q][0], u01 = U[l][q][1];
            const float2 u10 = U[l][q][2], u11 = U[l][q][3];
            float2 na, nb;
            na.x = u00.x * a.x - u00.y * a.y + u01.x * c.x - u01.y * c.y;
            na.y = u00.x * a.y + u00.y * a.x + u01.x * c.y + u01.y * c.x;
            nb.x = u10.x * a.x - u10.y * a.y + u11.x * c.x - u11.y * c.y;
            nb.y = u10.x * a.y + u10.y * a.x + u11.x * c.y + u11.y * c.x;
            s[i0] = na;                           // pairs are disjoint: in-place safe
            s[i1] = nb;
            __syncthreads();
        }

        // ---- CNOT ring = single bit-permutation (suffix-XOR over index bits) ----
        {
            const int v0 = t, v1 = t + NT;
            float2 a0 = s[v0], a1 = s[v1];
            int y0 = v0 ^ (v0 >> 1); y0 ^= y0 >> 2; y0 ^= y0 >> 4; y0 ^= y0 >> 8;
            int y1 = v1 ^ (v1 >> 1); y1 ^= y1 >> 2; y1 ^= y1 >> 4; y1 ^= y1 >> 8;
            const int j0 = (y0 & 0x1FF) | (((y0 ^ (v0 >> 9)) & 1) << 9);
            const int j1 = (y1 & 0x1FF) | (((y1 ^ (v1 >> 9)) & 1) << 9);
            __syncthreads();
            s[j0] = a0;
            s[j1] = a1;
            __syncthreads();
        }
    }

    // ---- measurement: <Z_q> = sum_i |s_i|^2 * (1 - 2*bit_{9-q}(i)) ----
    if (t < NQ) zsum[t] = 0.f;
    const float2 s0 = s[t], s1 = s[t + NT];
    const float p0 = s0.x * s0.x + s0.y * s0.y;
    const float p1 = s1.x * s1.x + s1.y * s1.y;
    __syncthreads();

    float z[NQ];
    #pragma unroll
    for (int q = 0; q < NQ; ++q) {
        const int p = 9 - q;
        const float t0 = ((t        >> p) & 1) ? -p0 : p0;
        const float t1 = (((t + NT) >> p) & 1) ? -p1 : p1;
        z[q] = t0 + t1;
    }
    #pragma unroll
    for (int q = 0; q < NQ; ++q) {
        float v = z[q];
        v += __shfl_xor_sync(0xFFFFFFFF, v, 16);
        v += __shfl_xor_sync(0xFFFFFFFF, v, 8);
        v += __shfl_xor_sync(0xFFFFFFFF, v, 4);
        v += __shfl_xor_sync(0xFFFFFFFF, v, 2);
        v += __shfl_xor_sync(0xFFFFFFFF, v, 1);
        if ((t & 31) == 0) atomicAdd(&zsum[q], v);
    }
    __syncthreads();
    if (t < NQ) out[b * NQ + t] = zsum[t];
}

extern "C" void kernel_launch(void* const* d_in, const int* in_sizes, int n_in,
                              void* d_out, int out_size) {
    const float* inputs  = (const float*)d_in[0];
    const float* weights = (const float*)d_in[1];
    float* out = (float*)d_out;
    const int B = in_sizes[0] / NQ;
    qsim_kernel<<<B, NT>>>(inputs, weights, out);
}

// round 4
// speedup vs baseline: 1.4290x; 1.4290x over previous
#include <cuda_runtime.h>
#include <math.h>

#define NQ  10
#define DIM 1024
#define NL  4
#define NT  256

__device__ __forceinline__ float2 cmul(float2 a, float2 b) {
    return make_float2(a.x * b.x - a.y * b.y, a.x * b.y + a.y * b.x);
}
__device__ __forceinline__ float2 cfma(float2 w, float2 a, float2 acc) {
    acc.x = fmaf(w.x, a.x, fmaf(-w.y, a.y, acc.x));
    acc.y = fmaf(w.x, a.y, fmaf( w.y, a.x, acc.y));
    return acc;
}

__global__ __launch_bounds__(NT) void qsim_kernel(
    const float* __restrict__ inputs,   // [B, 10]
    const float* __restrict__ weights,  // [4, 10, 3]
    float* __restrict__ out)            // [B, 10]
{
    // gate-bit pairings per sweep: (PL, PH) bit positions (bit 9 = qubit 0)
    constexpr int PL[5] = {0, 2, 3, 4, 6};
    constexpr int PH[5] = {1, 8, 9, 5, 7};

    __shared__ float2 s[DIM];                         // statevector, 8 KB
    __shared__ float2 U2[NL][NQ][4];                  // per-(layer,qubit) 2x2
    __shared__ __align__(16) float2 W[NL][5][16];     // fused 4x4 per (layer,pair)
    __shared__ float  zsum[NQ];

    const int b = blockIdx.x;
    const int t = threadIdx.x;

    // init |0...0>
    #pragma unroll
    for (int k = 0; k < 4; ++k) s[t + k * NT] = make_float2(0.f, 0.f);
    if (t == 0) s[0] = make_float2(1.f, 0.f);

    // ---- phase 1: fused 2x2  U2[l][q] = RZ(w2) RY(w1) RX(w0) RY(x_q) ----
    if (t < NL * NQ) {
        const int l = t / NQ;
        const int q = t % NQ;
        float x = inputs[b * NQ + q];
        x = fminf(fmaxf(x, -3.14159265358979323846f), 3.14159265358979323846f);
        float sx, cx; sincosf(0.5f * x, &sx, &cx);
        const float* w = weights + (l * NQ + q) * 3;
        float sa, ca; sincosf(0.5f * w[0], &sa, &ca);
        float sb, cb; sincosf(0.5f * w[1], &sb, &cb);
        float sc, cc; sincosf(0.5f * w[2], &sc, &cc);
        // M1 = RX(a) * RY(x)
        float2 m00 = make_float2( ca * cx, -sa * sx);
        float2 m01 = make_float2(-ca * sx, -sa * cx);
        float2 m10 = make_float2( ca * sx, -sa * cx);
        float2 m11 = make_float2( ca * cx,  sa * sx);
        // M2 = RY(b) * M1
        float2 n00 = make_float2(cb * m00.x - sb * m10.x, cb * m00.y - sb * m10.y);
        float2 n01 = make_float2(cb * m01.x - sb * m11.x, cb * m01.y - sb * m11.y);
        float2 n10 = make_float2(sb * m00.x + cb * m10.x, sb * m00.y + cb * m10.y);
        float2 n11 = make_float2(sb * m01.x + cb * m11.x, sb * m01.y + cb * m11.y);
        // M3 = RZ(c) * M2
        float2 e0 = make_float2(cc, -sc), e1 = make_float2(cc, sc);
        U2[l][q][0] = cmul(e0, n00);
        U2[l][q][1] = cmul(e0, n01);
        U2[l][q][2] = cmul(e1, n10);
        U2[l][q][3] = cmul(e1, n11);
    }
    __syncthreads();

    // ---- phase 2: fused 4x4  W[l][ps][i*4+j] = Uhi[bh][bh'] * Ulo[bl][bl'] ----
    #pragma unroll
    for (int ps = 0; ps < 5; ++ps) {
        const int qlo = 9 - PL[ps], qhi = 9 - PH[ps];
        // 64 entries per pair-slot across layers; threads 0..63 of each chunk
        if (t < NL * 16) {
            const int l = t >> 4;
            const int c = t & 15;
            const int i = c >> 2, j = c & 3;       // out cell, in cell
            W[l][ps][c] = cmul(U2[l][qhi][((i >> 1) << 1) | (j >> 1)],
                               U2[l][qlo][((i &  1) << 1) | (j &  1)]);
        }
    }
    __syncthreads();

    for (int l = 0; l < NL; ++l) {
        // ---- 5 fused two-qubit sweeps; groups disjoint per thread ----
        #pragma unroll
        for (int ps = 0; ps < 5; ++ps) {
            const int pl = PL[ps], ph = PH[ps];
            float2 a0, a1, a2, a3;
            int base = 0;
            if (ps == 0) {
                // bits (0,1): 4 consecutive amps -> conflict-free float4
                const float4* s4 = (const float4*)s;
                float4 v0 = s4[2 * t], v1 = s4[2 * t + 1];
                a0 = make_float2(v0.x, v0.y); a1 = make_float2(v0.z, v0.w);
                a2 = make_float2(v1.x, v1.y); a3 = make_float2(v1.z, v1.w);
            } else {
                const int low  = t & ((1 << pl) - 1);
                const int mid  = (t >> pl) & ((1 << (ph - pl - 1)) - 1);
                const int high = t >> (ph - 1);
                base = low | (mid << (pl + 1)) | (high << (ph + 1));
                a0 = s[base];
                a1 = s[base + (1 << pl)];
                a2 = s[base + (1 << ph)];
                a3 = s[base + (1 << ph) + (1 << pl)];
            }
            const float2* Wp = W[l][ps];
            float2 o0, o1, o2, o3;
            o0 = cmul(Wp[0],  a0); o0 = cfma(Wp[1],  a1, o0); o0 = cfma(Wp[2],  a2, o0); o0 = cfma(Wp[3],  a3, o0);
            o1 = cmul(Wp[4],  a0); o1 = cfma(Wp[5],  a1, o1); o1 = cfma(Wp[6],  a2, o1); o1 = cfma(Wp[7],  a3, o1);
            o2 = cmul(Wp[8],  a0); o2 = cfma(Wp[9],  a1, o2); o2 = cfma(Wp[10], a2, o2); o2 = cfma(Wp[11], a3, o2);
            o3 = cmul(Wp[12], a0); o3 = cfma(Wp[13], a1, o3); o3 = cfma(Wp[14], a2, o3); o3 = cfma(Wp[15], a3, o3);
            if (ps == 0) {
                float4* s4 = (float4*)s;
                s4[2 * t]     = make_float4(o0.x, o0.y, o1.x, o1.y);
                s4[2 * t + 1] = make_float4(o2.x, o2.y, o3.x, o3.y);
            } else {
                s[base]                         = o0;
                s[base + (1 << pl)]             = o1;
                s[base + (1 << ph)]             = o2;
                s[base + (1 << ph) + (1 << pl)] = o3;
            }
            __syncthreads();
        }

        // ---- CNOT ring = single bit-permutation (suffix-XOR over index bits) ----
        {
            float2 a[4]; int j[4];
            #pragma unroll
            for (int k = 0; k < 4; ++k) {
                const int v = t + k * NT;
                a[k] = s[v];
                int y = v ^ (v >> 1); y ^= y >> 2; y ^= y >> 4; y ^= y >> 8;
                j[k] = (y & 0x1FF) | (((y ^ (v >> 9)) & 1) << 9);
            }
            __syncthreads();
            #pragma unroll
            for (int k = 0; k < 4; ++k) s[j[k]] = a[k];
            __syncthreads();
        }
    }

    // ---- measurement: <Z_q> = sum_i |s_i|^2 * (1 - 2*bit_{9-q}(i)) ----
    if (t < NQ) zsum[t] = 0.f;
    float p[4];
    #pragma unroll
    for (int k = 0; k < 4; ++k) {
        const float2 v = s[t + k * NT];
        p[k] = v.x * v.x + v.y * v.y;
    }
    __syncthreads();

    float z[NQ];
    #pragma unroll
    for (int q = 0; q < NQ; ++q) {
        const int pbit = 9 - q;
        float acc = 0.f;
        #pragma unroll
        for (int k = 0; k < 4; ++k) {
            const int v = t + k * NT;
            acc += ((v >> pbit) & 1) ? -p[k] : p[k];
        }
        z[q] = acc;
    }
    #pragma unroll
    for (int q = 0; q < NQ; ++q) {
        float v = z[q];
        v += __shfl_xor_sync(0xFFFFFFFF, v, 16);
        v += __shfl_xor_sync(0xFFFFFFFF, v, 8);
        v += __shfl_xor_sync(0xFFFFFFFF, v, 4);
        v += __shfl_xor_sync(0xFFFFFFFF, v, 2);
        v += __shfl_xor_sync(0xFFFFFFFF, v, 1);
        if ((t & 31) == 0) atomicAdd(&zsum[q], v);
    }
    __syncthreads();
    if (t < NQ) out[b * NQ + t] = zsum[t];
}

extern "C" void kernel_launch(void* const* d_in, const int* in_sizes, int n_in,
                              void* d_out, int out_size) {
    const float* inputs  = (const float*)d_in[0];
    const float* weights = (const float*)d_in[1];
    float* out = (float*)d_out;
    const int B = in_sizes[0] / NQ;
    qsim_kernel<<<B, NT>>>(inputs, weights, out);
}